// round 4
// baseline (speedup 1.0000x reference)
#include <cuda_runtime.h>
#include <cuda_bf16.h>
#include <cstdint>
#include <math.h>

#define NB 2
#define NC 256
#define NH 128
#define NW 512
#define KC 16
#define NCHUNK (NC / KC)      // 16
#define TM 64                 // w1 rows per CTA
#define NTHREADS 512
#define ROWB 48               // padded smem row stride (32B data + 16B pad)

#define AH_OFF 0
#define AL_OFF (TM * ROWB)               // 3072
#define BH_OFF (2 * TM * ROWB)           // 6144
#define BL_OFF (BH_OFF + NW * ROWB)      // 30720
#define BUFB   (BL_OFF + NW * ROWB)      // 55296
#define PART_OFF (2 * BUFB)              // 110592
#define SMEM_BYTES (PART_OFF + TM * 8 * 3 * 4)   // + 6144

static __device__ __forceinline__ uint32_t s2u(const void* p) {
    uint32_t a;
    asm("{ .reg .u64 t; cvta.to.shared.u64 t, %1; cvt.u32.u64 %0, t; }" : "=r"(a) : "l"(p));
    return a;
}

#define LDSM4(r, addr) \
    asm volatile("ldmatrix.sync.aligned.m8n8.x4.shared.b16 {%0,%1,%2,%3}, [%4];" \
        : "=r"((r)[0]), "=r"((r)[1]), "=r"((r)[2]), "=r"((r)[3]) : "r"(addr))

#define MMA(acc, a, b0, b1) \
    asm volatile("mma.sync.aligned.m16n8k16.row.col.f32.bf16.bf16.f32 " \
        "{%0,%1,%2,%3}, {%4,%5,%6,%7}, {%8,%9}, {%0,%1,%2,%3};" \
        : "+f"((acc)[0]), "+f"((acc)[1]), "+f"((acc)[2]), "+f"((acc)[3]) \
        : "r"((a)[0]), "r"((a)[1]), "r"((a)[2]), "r"((a)[3]), "r"(b0), "r"(b1))

// fp32 -> (hi = truncated bf16, lo = rn-bf16 of exact residual)
static __device__ __forceinline__ void cvt_pair(float f0, float f1,
                                                uint32_t& hw, uint32_t& lw) {
    uint32_t u0 = __float_as_uint(f0), u1 = __float_as_uint(f1);
    hw = __byte_perm(u0, u1, 0x7632);
    float l0 = f0 - __uint_as_float(u0 & 0xFFFF0000u);
    float l1 = f1 - __uint_as_float(u1 & 0xFFFF0000u);
    __nv_bfloat162 p = __floats2bfloat162_rn(l0, l1);
    lw = *(uint32_t*)&p;
}

// convert+store one chunk's staged values into buffer bb
static __device__ __forceinline__ void store_chunk(char* bb, const float* stB,
                                                   float a0, float a1,
                                                   int t, int ar, int ac) {
    uint32_t hw[8], lw[8];
    #pragma unroll
    for (int j = 0; j < 8; j++) cvt_pair(stB[2*j], stB[2*j+1], hw[j], lw[j]);
    *(uint4*)(bb + BH_OFF + t * ROWB)      = make_uint4(hw[0], hw[1], hw[2], hw[3]);
    *(uint4*)(bb + BH_OFF + t * ROWB + 16) = make_uint4(hw[4], hw[5], hw[6], hw[7]);
    *(uint4*)(bb + BL_OFF + t * ROWB)      = make_uint4(lw[0], lw[1], lw[2], lw[3]);
    *(uint4*)(bb + BL_OFF + t * ROWB + 16) = make_uint4(lw[4], lw[5], lw[6], lw[7]);
    uint32_t ahw, alw;
    cvt_pair(a0, a1, ahw, alw);
    *(uint32_t*)(bb + AH_OFF + ar * ROWB + ac * 2) = ahw;
    *(uint32_t*)(bb + AL_OFF + ar * ROWB + ac * 2) = alw;
}

__global__ __launch_bounds__(NTHREADS, 1)
void cost_volume_mma(const float* __restrict__ img1, const float* __restrict__ img2,
                     const float* __restrict__ intri1, const float* __restrict__ extri1,
                     const float* __restrict__ extri2, float* __restrict__ out, int nout)
{
    extern __shared__ char smem[];
    const uint32_t smem_u = s2u(smem);
    const int t = threadIdx.x;
    const int lane = t & 31, wid = t >> 5;
    const int wm = wid & 1, wn = wid >> 1;     // 2x8 warp grid: 32-row m-band, 64-col n-slice

    const int cta = blockIdx.x;                // bh*8 + tile (tiles of same bh adjacent)
    const int tile = cta & 7;
    const int bh = cta >> 3;
    const int h = bh & (NH - 1);
    const int b = bh >> 7;
    const int w1_0 = tile * TM;

    const size_t cstr = (size_t)NH * NW;
    const float* g1 = img1 + ((size_t)b * NC * NH + h) * NW + w1_0;
    const float* g2 = img2 + ((size_t)b * NC * NH + h) * NW;

    // A-load assignment: row = t&63, channel pair = 2*(t>>6)
    const int ar = t & 63, ac = (t >> 6) * 2;
    const float* srcA = g1 + ar;
    const float* srcB = g2 + t;                // B row = w2 = t

    float acc[64];                             // [m2][g4][n2][4]
    #pragma unroll
    for (int i = 0; i < 64; i++) acc[i] = 0.f;

    float stB[KC], stA0, stA1;

    // ---- prologue: chunk 0 ----
    #pragma unroll
    for (int j = 0; j < KC; j++) stB[j] = __ldg(srcB + (size_t)j * cstr);
    stA0 = __ldg(srcA + (size_t)ac * cstr);
    stA1 = __ldg(srcA + (size_t)(ac + 1) * cstr);
    store_chunk(smem, stB, stA0, stA1, t, ar, ac);
    __syncthreads();

    const uint32_t lrow = (uint32_t)(lane & 15) * ROWB + (lane >> 4) * 16;
    const uint32_t aoff0 = (uint32_t)(wm * 32) * ROWB + lrow;        // m-tile 0
    const uint32_t aoff1 = aoff0 + 16 * ROWB;                        // m-tile 1
    const uint32_t boff  = (uint32_t)(wn * 64) * ROWB + lrow;

    for (int chunk = 0; chunk < NCHUNK; chunk++) {
        // issue next chunk's global loads first (latency overlaps MMA below)
        if (chunk + 1 < NCHUNK) {
            const int k0 = (chunk + 1) * KC;
            #pragma unroll
            for (int j = 0; j < KC; j++) stB[j] = __ldg(srcB + (size_t)(k0 + j) * cstr);
            stA0 = __ldg(srcA + (size_t)(k0 + ac) * cstr);
            stA1 = __ldg(srcA + (size_t)(k0 + ac + 1) * cstr);
        }

        const uint32_t base = smem_u + (uint32_t)(chunk & 1) * BUFB;
        uint32_t Ah0[4], Al0[4], Ah1[4], Al1[4];
        LDSM4(Ah0, base + AH_OFF + aoff0);
        LDSM4(Ah1, base + AH_OFF + aoff1);
        LDSM4(Al0, base + AL_OFF + aoff0);
        LDSM4(Al1, base + AL_OFF + aoff1);
        #pragma unroll
        for (int g = 0; g < 4; g++) {
            uint32_t Bh[4], Bl[4];
            LDSM4(Bh, base + BH_OFF + boff + g * 16 * ROWB);
            LDSM4(Bl, base + BL_OFF + boff + g * 16 * ROWB);
            float* a00 = acc + ((0 * 4 + g) * 2 + 0) * 4;
            float* a01 = acc + ((0 * 4 + g) * 2 + 1) * 4;
            float* a10 = acc + ((1 * 4 + g) * 2 + 0) * 4;
            float* a11 = acc + ((1 * 4 + g) * 2 + 1) * 4;
            // pass-major: same-accumulator distance = 4 MMAs
            MMA(a00, Ah0, Bh[0], Bh[2]);
            MMA(a01, Ah0, Bh[1], Bh[3]);
            MMA(a10, Ah1, Bh[0], Bh[2]);
            MMA(a11, Ah1, Bh[1], Bh[3]);
            MMA(a00, Ah0, Bl[0], Bl[2]);
            MMA(a01, Ah0, Bl[1], Bl[3]);
            MMA(a10, Ah1, Bl[0], Bl[2]);
            MMA(a11, Ah1, Bl[1], Bl[3]);
            MMA(a00, Al0, Bh[0], Bh[2]);
            MMA(a01, Al0, Bh[1], Bh[3]);
            MMA(a10, Al1, Bh[0], Bh[2]);
            MMA(a11, Al1, Bh[1], Bh[3]);
        }

        if (chunk + 1 < NCHUNK)
            store_chunk(smem + ((chunk + 1) & 1) * BUFB, stB, stA0, stA1, t, ar, ac);
        __syncthreads();
    }

    // ---- epilogue: softmax stats straight from register accumulators ----
    const float scale = 0.0625f;   // 1/sqrt(256)
    float* part = (float*)(smem + PART_OFF);   // [64 rows][8 wn][3]
    #pragma unroll
    for (int m = 0; m < 2; m++) {
        const int r0 = wm * 32 + m * 16 + (lane >> 2);   // rows r0, r0+8
        const int w1g0 = w1_0 + r0, w1g1 = w1g0 + 8;
        float Z0 = 0.f, S0 = 0.f, M0 = 0.f, Z1 = 0.f, S1 = 0.f, M1 = 0.f;
        #pragma unroll
        for (int g = 0; g < 4; g++)
            #pragma unroll
            for (int n = 0; n < 2; n++) {
                const float* a = acc + ((m * 4 + g) * 2 + n) * 4;
                const int c0 = wn * 64 + g * 16 + n * 8 + (lane & 3) * 2;
                float e;
                e = __expf(a[0] * scale); Z0 += e;
                if (c0     <= w1g0) { S0 += e * (float)c0;       M0 = fmaxf(M0, e); }
                e = __expf(a[1] * scale); Z0 += e;
                if (c0 + 1 <= w1g0) { S0 += e * (float)(c0 + 1); M0 = fmaxf(M0, e); }
                e = __expf(a[2] * scale); Z1 += e;
                if (c0     <= w1g1) { S1 += e * (float)c0;       M1 = fmaxf(M1, e); }
                e = __expf(a[3] * scale); Z1 += e;
                if (c0 + 1 <= w1g1) { S1 += e * (float)(c0 + 1); M1 = fmaxf(M1, e); }
            }
        #pragma unroll
        for (int off = 1; off <= 2; off <<= 1) {
            Z0 += __shfl_xor_sync(0xffffffffu, Z0, off);
            S0 += __shfl_xor_sync(0xffffffffu, S0, off);
            M0 = fmaxf(M0, __shfl_xor_sync(0xffffffffu, M0, off));
            Z1 += __shfl_xor_sync(0xffffffffu, Z1, off);
            S1 += __shfl_xor_sync(0xffffffffu, S1, off);
            M1 = fmaxf(M1, __shfl_xor_sync(0xffffffffu, M1, off));
        }
        if ((lane & 3) == 0) {
            int i0 = (r0 * 8 + wn) * 3, i1 = ((r0 + 8) * 8 + wn) * 3;
            part[i0] = Z0; part[i0+1] = S0; part[i0+2] = M0;
            part[i1] = Z1; part[i1+1] = S1; part[i1+2] = M1;
        }
    }
    __syncthreads();

    if (t < TM) {
        float Zt = 0.f, St = 0.f, Mt = 0.f;
        #pragma unroll
        for (int g = 0; g < 8; g++) {
            const int q = (t * 8 + g) * 3;
            Zt += part[q]; St += part[q+1]; Mt = fmaxf(Mt, part[q+2]);
        }
        const float fx = __ldg(intri1 + b * 9);
        const float dx = __ldg(extri1 + b * 16 + 3)  - __ldg(extri2 + b * 16 + 3);
        const float dy = __ldg(extri1 + b * 16 + 7)  - __ldg(extri2 + b * 16 + 7);
        const float dz = __ldg(extri1 + b * 16 + 11) - __ldg(extri2 + b * 16 + 11);
        const float fb = fx * sqrtf(dx * dx + dy * dy + dz * dz);
        const float inv = 1.f / Zt;
        const float corresp = St * inv;
        const float conf = Mt * inv;
        float disp = fmaxf(fabsf(corresp - (float)(w1_0 + t)) * (1.0f / NW), 0.1f);
        const int oidx = (b * NH + h) * NW + w1_0 + t;
        out[oidx] = fb / disp;
        out[nout + oidx] = conf;
    }
}

extern "C" void kernel_launch(void* const* d_in, const int* in_sizes, int n_in,
                              void* d_out, int out_size) {
    const float* img1   = (const float*)d_in[0];
    const float* img2   = (const float*)d_in[1];
    const float* intri1 = (const float*)d_in[2];
    const float* extri1 = (const float*)d_in[4];
    const float* extri2 = (const float*)d_in[5];
    float* out = (float*)d_out;
    const int nout = out_size / 2;

    cudaFuncSetAttribute(cost_volume_mma,
                         cudaFuncAttributeMaxDynamicSharedMemorySize, SMEM_BYTES);
    dim3 grid(NB * NH * (NW / TM));   // 2048 CTAs
    cost_volume_mma<<<grid, NTHREADS, SMEM_BYTES>>>(
        img1, img2, intri1, extri1, extri2, out, nout);
}

// round 5
// speedup vs baseline: 1.3143x; 1.3143x over previous
#include <cuda_runtime.h>
#include <cuda_fp16.h>
#include <cstdint>
#include <math.h>

#define NB 2
#define NC 256
#define NH 128
#define NW 512
#define KC 16
#define NCHUNK (NC / KC)      // 16
#define TM 64                 // w1 rows per CTA
#define NTHREADS 512
#define ROWB 48               // padded smem row stride (32B data + 16B pad)

#define AH_OFF 0
#define AL_OFF (TM * ROWB)               // 3072
#define BH_OFF (2 * TM * ROWB)           // 6144
#define BUFB   (BH_OFF + NW * ROWB)      // 30720
#define PART_OFF (2 * BUFB)              // 61440
#define SMEM_BYTES (PART_OFF + TM * 8 * 3 * 4)   // 67584

static __device__ __forceinline__ uint32_t s2u(const void* p) {
    uint32_t a;
    asm("{ .reg .u64 t; cvta.to.shared.u64 t, %1; cvt.u32.u64 %0, t; }" : "=r"(a) : "l"(p));
    return a;
}

#define LDSM4(r, addr) \
    asm volatile("ldmatrix.sync.aligned.m8n8.x4.shared.b16 {%0,%1,%2,%3}, [%4];" \
        : "=r"((r)[0]), "=r"((r)[1]), "=r"((r)[2]), "=r"((r)[3]) : "r"(addr))

#define MMA(acc, a, b0, b1) \
    asm volatile("mma.sync.aligned.m16n8k16.row.col.f32.f16.f16.f32 " \
        "{%0,%1,%2,%3}, {%4,%5,%6,%7}, {%8,%9}, {%0,%1,%2,%3};" \
        : "+f"((acc)[0]), "+f"((acc)[1]), "+f"((acc)[2]), "+f"((acc)[3]) \
        : "r"((a)[0]), "r"((a)[1]), "r"((a)[2]), "r"((a)[3]), "r"(b0), "r"(b1))

// convert+store one chunk's staged values into buffer bb
// B: fp16-rounded hi only. A: hi + exact-residual lo.
static __device__ __forceinline__ void store_chunk(char* bb, const float* stB,
                                                   float a0, float a1,
                                                   int t, int ar, int ac) {
    uint32_t hw[8];
    #pragma unroll
    for (int j = 0; j < 8; j++) {
        __half2 p = __floats2half2_rn(stB[2*j], stB[2*j+1]);
        hw[j] = *(uint32_t*)&p;
    }
    *(uint4*)(bb + BH_OFF + t * ROWB)      = make_uint4(hw[0], hw[1], hw[2], hw[3]);
    *(uint4*)(bb + BH_OFF + t * ROWB + 16) = make_uint4(hw[4], hw[5], hw[6], hw[7]);

    __half h0 = __float2half_rn(a0), h1 = __float2half_rn(a1);
    float l0 = a0 - __half2float(h0), l1 = a1 - __half2float(h1);
    __half2 hh = __halves2half2(h0, h1);
    __half2 ll = __floats2half2_rn(l0, l1);
    *(uint32_t*)(bb + AH_OFF + ar * ROWB + ac * 2) = *(uint32_t*)&hh;
    *(uint32_t*)(bb + AL_OFF + ar * ROWB + ac * 2) = *(uint32_t*)&ll;
}

__global__ __launch_bounds__(NTHREADS, 1)
void cost_volume_mma(const float* __restrict__ img1, const float* __restrict__ img2,
                     const float* __restrict__ intri1, const float* __restrict__ extri1,
                     const float* __restrict__ extri2, float* __restrict__ out, int nout)
{
    extern __shared__ char smem[];
    const uint32_t smem_u = s2u(smem);
    const int t = threadIdx.x;
    const int lane = t & 31, wid = t >> 5;
    const int wm = wid & 1, wn = wid >> 1;     // 2x8 warp grid: 32-row m-band, 64-col n-slice

    const int cta = blockIdx.x;                // bh*8 + tile (tiles of same bh adjacent)
    const int tile = cta & 7;
    const int bh = cta >> 3;
    const int h = bh & (NH - 1);
    const int b = bh >> 7;
    const int w1_0 = tile * TM;

    const size_t cstr = (size_t)NH * NW;
    const float* g1 = img1 + ((size_t)b * NC * NH + h) * NW + w1_0;
    const float* g2 = img2 + ((size_t)b * NC * NH + h) * NW;

    const int ar = t & 63, ac = (t >> 6) * 2;
    const float* srcA = g1 + ar;
    const float* srcB = g2 + t;

    float acc[64];                             // [m2][g4][n2][4]
    #pragma unroll
    for (int i = 0; i < 64; i++) acc[i] = 0.f;

    float stB[KC], stA0, stA1;

    // ---- prologue: chunk 0 ----
    #pragma unroll
    for (int j = 0; j < KC; j++) stB[j] = __ldg(srcB + (size_t)j * cstr);
    stA0 = __ldg(srcA + (size_t)ac * cstr);
    stA1 = __ldg(srcA + (size_t)(ac + 1) * cstr);
    store_chunk(smem, stB, stA0, stA1, t, ar, ac);
    __syncthreads();

    const uint32_t lrow = (uint32_t)(lane & 15) * ROWB + (lane >> 4) * 16;
    const uint32_t aoff0 = (uint32_t)(wm * 32) * ROWB + lrow;        // m-tile 0
    const uint32_t aoff1 = aoff0 + 16 * ROWB;                        // m-tile 1
    const uint32_t boff  = (uint32_t)(wn * 64) * ROWB + lrow;

    for (int chunk = 0; chunk < NCHUNK; chunk++) {
        // issue next chunk's global loads first (latency hides under MMA below)
        if (chunk + 1 < NCHUNK) {
            const int k0 = (chunk + 1) * KC;
            #pragma unroll
            for (int j = 0; j < KC; j++) stB[j] = __ldg(srcB + (size_t)(k0 + j) * cstr);
            stA0 = __ldg(srcA + (size_t)(k0 + ac) * cstr);
            stA1 = __ldg(srcA + (size_t)(k0 + ac + 1) * cstr);
        }

        const uint32_t base = smem_u + (uint32_t)(chunk & 1) * BUFB;
        uint32_t Ah0[4], Al0[4], Ah1[4], Al1[4];
        LDSM4(Ah0, base + AH_OFF + aoff0);
        LDSM4(Ah1, base + AH_OFF + aoff1);
        LDSM4(Al0, base + AL_OFF + aoff0);
        LDSM4(Al1, base + AL_OFF + aoff1);
        #pragma unroll
        for (int g = 0; g < 4; g++) {
            uint32_t Bh[4];
            LDSM4(Bh, base + BH_OFF + boff + g * 16 * ROWB);
            float* a00 = acc + ((0 * 4 + g) * 2 + 0) * 4;
            float* a01 = acc + ((0 * 4 + g) * 2 + 1) * 4;
            float* a10 = acc + ((1 * 4 + g) * 2 + 0) * 4;
            float* a11 = acc + ((1 * 4 + g) * 2 + 1) * 4;
            // same-accumulator distance = 4 MMAs
            MMA(a00, Ah0, Bh[0], Bh[2]);
            MMA(a01, Ah0, Bh[1], Bh[3]);
            MMA(a10, Ah1, Bh[0], Bh[2]);
            MMA(a11, Ah1, Bh[1], Bh[3]);
            MMA(a00, Al0, Bh[0], Bh[2]);
            MMA(a01, Al0, Bh[1], Bh[3]);
            MMA(a10, Al1, Bh[0], Bh[2]);
            MMA(a11, Al1, Bh[1], Bh[3]);
        }

        if (chunk + 1 < NCHUNK)
            store_chunk(smem + ((chunk + 1) & 1) * BUFB, stB, stA0, stA1, t, ar, ac);
        __syncthreads();
    }

    // ---- epilogue: softmax stats straight from register accumulators ----
    const float scale = 0.0625f;   // 1/sqrt(256)
    float* part = (float*)(smem + PART_OFF);   // [64 rows][8 wn][3]
    #pragma unroll
    for (int m = 0; m < 2; m++) {
        const int r0 = wm * 32 + m * 16 + (lane >> 2);   // rows r0, r0+8
        const int w1g0 = w1_0 + r0, w1g1 = w1g0 + 8;
        float Z0 = 0.f, S0 = 0.f, M0 = 0.f, Z1 = 0.f, S1 = 0.f, M1 = 0.f;
        #pragma unroll
        for (int g = 0; g < 4; g++)
            #pragma unroll
            for (int n = 0; n < 2; n++) {
                const float* a = acc + ((m * 4 + g) * 2 + n) * 4;
                const int c0 = wn * 64 + g * 16 + n * 8 + (lane & 3) * 2;
                float e;
                e = __expf(a[0] * scale); Z0 += e;
                if (c0     <= w1g0) { S0 += e * (float)c0;       M0 = fmaxf(M0, e); }
                e = __expf(a[1] * scale); Z0 += e;
                if (c0 + 1 <= w1g0) { S0 += e * (float)(c0 + 1); M0 = fmaxf(M0, e); }
                e = __expf(a[2] * scale); Z1 += e;
                if (c0     <= w1g1) { S1 += e * (float)c0;       M1 = fmaxf(M1, e); }
                e = __expf(a[3] * scale); Z1 += e;
                if (c0 + 1 <= w1g1) { S1 += e * (float)(c0 + 1); M1 = fmaxf(M1, e); }
            }
        #pragma unroll
        for (int off = 1; off <= 2; off <<= 1) {
            Z0 += __shfl_xor_sync(0xffffffffu, Z0, off);
            S0 += __shfl_xor_sync(0xffffffffu, S0, off);
            M0 = fmaxf(M0, __shfl_xor_sync(0xffffffffu, M0, off));
            Z1 += __shfl_xor_sync(0xffffffffu, Z1, off);
            S1 += __shfl_xor_sync(0xffffffffu, S1, off);
            M1 = fmaxf(M1, __shfl_xor_sync(0xffffffffu, M1, off));
        }
        if ((lane & 3) == 0) {
            int i0 = (r0 * 8 + wn) * 3, i1 = ((r0 + 8) * 8 + wn) * 3;
            part[i0] = Z0; part[i0+1] = S0; part[i0+2] = M0;
            part[i1] = Z1; part[i1+1] = S1; part[i1+2] = M1;
        }
    }
    __syncthreads();

    if (t < TM) {
        float Zt = 0.f, St = 0.f, Mt = 0.f;
        #pragma unroll
        for (int g = 0; g < 8; g++) {
            const int q = (t * 8 + g) * 3;
            Zt += part[q]; St += part[q+1]; Mt = fmaxf(Mt, part[q+2]);
        }
        const float fx = __ldg(intri1 + b * 9);
        const float dx = __ldg(extri1 + b * 16 + 3)  - __ldg(extri2 + b * 16 + 3);
        const float dy = __ldg(extri1 + b * 16 + 7)  - __ldg(extri2 + b * 16 + 7);
        const float dz = __ldg(extri1 + b * 16 + 11) - __ldg(extri2 + b * 16 + 11);
        const float fb = fx * sqrtf(dx * dx + dy * dy + dz * dz);
        const float inv = 1.f / Zt;
        const float corresp = St * inv;
        const float conf = Mt * inv;
        float disp = fmaxf(fabsf(corresp - (float)(w1_0 + t)) * (1.0f / NW), 0.1f);
        const int oidx = (b * NH + h) * NW + w1_0 + t;
        out[oidx] = fb / disp;
        out[nout + oidx] = conf;
    }
}

extern "C" void kernel_launch(void* const* d_in, const int* in_sizes, int n_in,
                              void* d_out, int out_size) {
    const float* img1   = (const float*)d_in[0];
    const float* img2   = (const float*)d_in[1];
    const float* intri1 = (const float*)d_in[2];
    const float* extri1 = (const float*)d_in[4];
    const float* extri2 = (const float*)d_in[5];
    float* out = (float*)d_out;
    const int nout = out_size / 2;

    cudaFuncSetAttribute(cost_volume_mma,
                         cudaFuncAttributeMaxDynamicSharedMemorySize, SMEM_BYTES);
    dim3 grid(NB * NH * (NW / TM));   // 2048 CTAs
    cost_volume_mma<<<grid, NTHREADS, SMEM_BYTES>>>(
        img1, img2, intri1, extri1, extri2, out, nout);
}